// round 4
// baseline (speedup 1.0000x reference)
#include <cuda_runtime.h>
#include <cstdint>
#include <cfloat>

#define NT       4096
#define NTRACES  512
#define CHANNELS 8
#define COLS     (NTRACES * CHANNELS)   // 4096
#define THREADS  512
#define IPT      8                      // 512*8 = 4096
#define NBINS    4096
#define CH_PER_BLK 2
#define NBLOCKS  (NTRACES * (CHANNELS / CH_PER_BLK))  // 2048

#define BIN_SCALE (4096.0f / 12.0f)
#define BINW      (12.0f / 4096.0f)

__device__ float        g_partials[NBLOCKS];
__device__ unsigned int g_done = 0;

// Process one (pred,obs) column pair held in registers. Returns this thread's
// contribution to  integral |F_p - F_o| dx  ==  sum_i |sp_i - so_i|.
// bufP/bufO: 4096-float scratch each. H: 4096 u32 packed histogram
// (low 16 = pred count, high 16 = obs count). All block-collective.
__device__ __forceinline__ float process_pair(const float* __restrict__ vp,
                                               const float* __restrict__ vo,
                                               float* __restrict__ bufP,
                                               float* __restrict__ bufO,
                                               unsigned* __restrict__ H,
                                               int tid)
{
    __shared__ unsigned wsum[THREADS / 32];

    // ---- zero packed histogram (vectorized) ----
    {
        uint4 z = make_uint4(0u, 0u, 0u, 0u);
        reinterpret_cast<uint4*>(H)[tid]           = z;
        reinterpret_cast<uint4*>(H)[tid + THREADS] = z;
    }
    __syncthreads();

    // ---- histogram; atomic returns intra-bucket rank (kept in regs) ----
    unsigned pk[IPT], ok[IPT];   // bin | rank<<16
    #pragma unroll
    for (int k = 0; k < IPT; ++k) {
        int b = __float2int_rd((vp[k] + 6.0f) * BIN_SCALE);
        b = min(max(b, 0), NBINS - 1);
        unsigned r = atomicAdd(&H[b], 1u) & 0xFFFFu;
        pk[k] = (unsigned)b | (r << 16);
    }
    #pragma unroll
    for (int k = 0; k < IPT; ++k) {
        int b = __float2int_rd((vo[k] + 6.0f) * BIN_SCALE);
        b = min(max(b, 0), NBINS - 1);
        unsigned r = atomicAdd(&H[b], 0x10000u) >> 16;
        ok[k] = (unsigned)b | (r << 16);
    }
    __syncthreads();

    // ---- packed exclusive scan of H in place (both fields at once) ----
    {
        unsigned loc[8];
        uint4 h0 = reinterpret_cast<uint4*>(H)[tid * 2];
        uint4 h1 = reinterpret_cast<uint4*>(H)[tid * 2 + 1];
        loc[0] = h0.x; loc[1] = h0.y; loc[2] = h0.z; loc[3] = h0.w;
        loc[4] = h1.x; loc[5] = h1.y; loc[6] = h1.z; loc[7] = h1.w;

        unsigned tsum = 0;
        #pragma unroll
        for (int k = 0; k < 8; ++k) { unsigned t = loc[k]; loc[k] = tsum; tsum += t; }

        const int lane = tid & 31, wid = tid >> 5;
        unsigned x = tsum;
        #pragma unroll
        for (int off = 1; off < 32; off <<= 1) {
            unsigned y = __shfl_up_sync(0xFFFFFFFFu, x, off);
            if (lane >= off) x += y;
        }
        if (lane == 31) wsum[wid] = x;
        __syncthreads();
        if (wid == 0) {
            unsigned w = (lane < THREADS / 32) ? wsum[lane] : 0u;
            #pragma unroll
            for (int off = 1; off < THREADS / 32; off <<= 1) {
                unsigned y = __shfl_up_sync(0xFFFFFFFFu, w, off);
                if (lane >= off) w += y;
            }
            if (lane < THREADS / 32) wsum[lane] = w;
        }
        __syncthreads();
        const unsigned base = (wid ? wsum[wid - 1] : 0u) + (x - tsum);
        #pragma unroll
        for (int k = 0; k < 8; ++k) loc[k] += base;
        reinterpret_cast<uint4*>(H)[tid * 2]     = make_uint4(loc[0], loc[1], loc[2], loc[3]);
        reinterpret_cast<uint4*>(H)[tid * 2 + 1] = make_uint4(loc[4], loc[5], loc[6], loc[7]);
    }
    __syncthreads();

    // ---- scatter (no atomics: prefix + saved rank) ----
    #pragma unroll
    for (int k = 0; k < IPT; ++k) {
        unsigned b = pk[k] & 0xFFFFu, r = pk[k] >> 16;
        bufP[(H[b] & 0xFFFFu) + r] = vp[k];
    }
    #pragma unroll
    for (int k = 0; k < IPT; ++k) {
        unsigned b = ok[k] & 0xFFFFu, r = ok[k] >> 16;
        bufO[(H[b] >> 16) + r] = vo[k];
    }
    __syncthreads();

    // ---- per-bucket exact CDF-integral walk ----
    float acc = 0.0f;
    #pragma unroll 1
    for (int b = tid; b < NBINS; b += THREADS) {
        const unsigned E0 = H[b];
        const unsigned E1 = (b < NBINS - 1) ? H[b + 1]
                                            : ((unsigned)NT | ((unsigned)NT << 16));
        const int sP = (int)(E0 & 0xFFFFu), eP = (int)(E1 & 0xFFFFu);
        const int sO = (int)(E0 >> 16),     eO = (int)(E1 >> 16);

        // exact within-bucket insertion sorts (avg ~1 element each)
        for (int i = sP + 1; i < eP; ++i) {
            float v = bufP[i]; int j = i - 1;
            while (j >= sP && bufP[j] > v) { bufP[j + 1] = bufP[j]; --j; }
            bufP[j + 1] = v;
        }
        for (int i = sO + 1; i < eO; ++i) {
            float v = bufO[i]; int j = i - 1;
            while (j >= sO && bufO[j] > v) { bufO[j + 1] = bufO[j]; --j; }
            bufO[j + 1] = v;
        }

        // merged walk: acc += |F_p - F_o| * segment_length
        float xprev = fmaf((float)b, BINW, -6.0f);
        const float xR = fmaf((float)(b + 1), BINW, -6.0f);
        int d = sP - sO;            // entering deficit (cumP - cumO)
        int ip = sP, io = sO;
        while (ip < eP || io < eO) {
            float xp = (ip < eP) ? bufP[ip] : FLT_MAX;
            float xo = (io < eO) ? bufO[io] : FLT_MAX;
            bool takeP = (xp <= xo);
            float x = takeP ? xp : xo;
            acc = fmaf((float)abs(d), x - xprev, acc);
            d += takeP ? 1 : -1;
            if (takeP) ++ip; else ++io;
            xprev = x;
        }
        acc = fmaf((float)abs(d), xR - xprev, acc);
    }
    __syncthreads();   // H / buffers reused by next pair
    return acc;
}

// Dynamic smem: bufP, bufO, H, stageP, stageO  ->  5 * 16KB = 80KB
__global__ __launch_bounds__(THREADS, 2)
void wass_cdf_kernel(const float* __restrict__ pred,
                     const float* __restrict__ obs,
                     float* __restrict__ out)
{
    extern __shared__ float smem[];
    float*    bufP   = smem;
    float*    bufO   = smem + 4096;
    unsigned* H      = reinterpret_cast<unsigned*>(smem + 8192);
    float*    stageP = smem + 12288;
    float*    stageO = smem + 16384;

    __shared__ float  sred[THREADS / 32];
    __shared__ double dred[THREADS / 32];
    __shared__ bool   s_last;

    const int tid  = threadIdx.x;
    const int tr   = blockIdx.x >> 2;
    const int c0   = (blockIdx.x & 3) * CH_PER_BLK;
    const int base = tr * CHANNELS + c0;

    // ---- load: float2 over 2 adjacent channels (L2 dedups 32B sectors).
    // ch0 -> registers, ch1 -> thread-private smem staging (no sync needed).
    float vp[IPT], vo[IPT];
    #pragma unroll
    for (int k = 0; k < IPT; ++k) {
        const int t = tid + k * THREADS;
        const size_t off = (size_t)t * COLS + base;
        float2 p = *reinterpret_cast<const float2*>(pred + off);
        float2 o = *reinterpret_cast<const float2*>(obs  + off);
        vp[k] = p.x; vo[k] = o.x;
        stageP[t] = p.y; stageO[t] = o.y;
    }

    float acc = process_pair(vp, vo, bufP, bufO, H, tid);

    #pragma unroll
    for (int k = 0; k < IPT; ++k) {
        const int t = tid + k * THREADS;
        vp[k] = stageP[t]; vo[k] = stageO[t];
    }
    acc += process_pair(vp, vo, bufP, bufO, H, tid);

    // ---- deterministic block reduction ----
    #pragma unroll
    for (int off = 16; off > 0; off >>= 1)
        acc += __shfl_xor_sync(0xFFFFFFFFu, acc, off);

    const int wid  = tid >> 5;
    const int lane = tid & 31;
    if (lane == 0) sred[wid] = acc;
    __syncthreads();

    if (wid == 0) {
        float v = (lane < THREADS / 32) ? sred[lane] : 0.0f;
        #pragma unroll
        for (int off = 8; off > 0; off >>= 1)
            v += __shfl_xor_sync(0xFFFFFFFFu, v, off);
        if (lane == 0) g_partials[blockIdx.x] = v;
    }

    // ---- last-block-done fused finalize (deterministic) ----
    if (tid == 0) {
        __threadfence();
        unsigned int t = atomicAdd(&g_done, 1u);
        s_last = (t == NBLOCKS - 1);
    }
    __syncthreads();

    if (s_last) {
        __threadfence();
        double d = 0.0;
        for (int i = tid; i < NBLOCKS; i += THREADS)
            d += (double)g_partials[i];
        #pragma unroll
        for (int off = 16; off > 0; off >>= 1)
            d += __shfl_xor_sync(0xFFFFFFFFu, d, off);
        if (lane == 0) dred[wid] = d;
        __syncthreads();
        if (wid == 0) {
            double v = (lane < THREADS / 32) ? dred[lane] : 0.0;
            #pragma unroll
            for (int off = 8; off > 0; off >>= 1)
                v += __shfl_xor_sync(0xFFFFFFFFu, v, off);
            if (lane == 0) {
                out[0] = (float)(v / ((double)NT * (double)COLS));
                g_done = 0;   // reset for next graph replay
            }
        }
    }
}

extern "C" void kernel_launch(void* const* d_in, const int* in_sizes, int n_in,
                              void* d_out, int out_size)
{
    const float* pred = (const float*)d_in[0];
    const float* obs  = (const float*)d_in[1];
    float* out = (float*)d_out;

    const size_t smem_bytes = 5 * 4096 * sizeof(float);   // 80KB
    cudaFuncSetAttribute(wass_cdf_kernel,
                         cudaFuncAttributeMaxDynamicSharedMemorySize,
                         (int)smem_bytes);

    wass_cdf_kernel<<<NBLOCKS, THREADS, smem_bytes>>>(pred, obs, out);
}

// round 5
// speedup vs baseline: 1.1603x; 1.1603x over previous
#include <cuda_runtime.h>
#include <cstdint>

#define NT       4096
#define NTRACES  512
#define CHANNELS 8
#define COLS     (NTRACES * CHANNELS)   // 4096
#define THREADS  512
#define IPT      8                      // 512*8 = 4096
#define NBINS    4096
#define CH_PER_BLK 2
#define NBLOCKS  (NTRACES * (CHANNELS / CH_PER_BLK))  // 2048

#define BIN_SCALE (4096.0f / 12.0f)

__device__ float        g_partials[NBLOCKS];
__device__ unsigned int g_done = 0;

// One (pred,obs) column pair, inputs in registers. Exact sort of both into
// bufP/bufO via packed counting sort, then coherent |diff| accumulation.
// H: 4096 u32 packed histogram (low16 = pred, high16 = obs). Block-collective.
__device__ __forceinline__ float process_pair(const float* __restrict__ vp,
                                               const float* __restrict__ vo,
                                               float* __restrict__ bufP,
                                               float* __restrict__ bufO,
                                               unsigned* __restrict__ H,
                                               int tid)
{
    __shared__ unsigned wsum[THREADS / 32];

    // ---- zero packed histogram (vectorized) ----
    {
        uint4 z = make_uint4(0u, 0u, 0u, 0u);
        reinterpret_cast<uint4*>(H)[tid]           = z;
        reinterpret_cast<uint4*>(H)[tid + THREADS] = z;
    }
    __syncthreads();

    // ---- histogram; atomic returns intra-bucket rank (kept in regs) ----
    unsigned pk[IPT], ok[IPT];   // bin | rank<<16
    #pragma unroll
    for (int k = 0; k < IPT; ++k) {
        int b = __float2int_rd((vp[k] + 6.0f) * BIN_SCALE);
        b = min(max(b, 0), NBINS - 1);
        unsigned r = atomicAdd(&H[b], 1u) & 0xFFFFu;
        pk[k] = (unsigned)b | (r << 16);
    }
    #pragma unroll
    for (int k = 0; k < IPT; ++k) {
        int b = __float2int_rd((vo[k] + 6.0f) * BIN_SCALE);
        b = min(max(b, 0), NBINS - 1);
        unsigned r = atomicAdd(&H[b], 0x10000u) >> 16;
        ok[k] = (unsigned)b | (r << 16);
    }
    __syncthreads();

    // ---- packed exclusive scan of H in place (both fields at once) ----
    {
        unsigned loc[8];
        uint4 h0 = reinterpret_cast<uint4*>(H)[tid * 2];
        uint4 h1 = reinterpret_cast<uint4*>(H)[tid * 2 + 1];
        loc[0] = h0.x; loc[1] = h0.y; loc[2] = h0.z; loc[3] = h0.w;
        loc[4] = h1.x; loc[5] = h1.y; loc[6] = h1.z; loc[7] = h1.w;

        unsigned tsum = 0;
        #pragma unroll
        for (int k = 0; k < 8; ++k) { unsigned t = loc[k]; loc[k] = tsum; tsum += t; }

        const int lane = tid & 31, wid = tid >> 5;
        unsigned x = tsum;
        #pragma unroll
        for (int off = 1; off < 32; off <<= 1) {
            unsigned y = __shfl_up_sync(0xFFFFFFFFu, x, off);
            if (lane >= off) x += y;
        }
        if (lane == 31) wsum[wid] = x;
        __syncthreads();
        if (wid == 0) {
            unsigned w = (lane < THREADS / 32) ? wsum[lane] : 0u;
            #pragma unroll
            for (int off = 1; off < THREADS / 32; off <<= 1) {
                unsigned y = __shfl_up_sync(0xFFFFFFFFu, w, off);
                if (lane >= off) w += y;
            }
            if (lane < THREADS / 32) wsum[lane] = w;
        }
        __syncthreads();
        const unsigned base = (wid ? wsum[wid - 1] : 0u) + (x - tsum);
        #pragma unroll
        for (int k = 0; k < 8; ++k) loc[k] += base;
        reinterpret_cast<uint4*>(H)[tid * 2]     = make_uint4(loc[0], loc[1], loc[2], loc[3]);
        reinterpret_cast<uint4*>(H)[tid * 2 + 1] = make_uint4(loc[4], loc[5], loc[6], loc[7]);
    }
    __syncthreads();

    // ---- scatter (no atomics: prefix + saved rank) ----
    #pragma unroll
    for (int k = 0; k < IPT; ++k) {
        unsigned b = pk[k] & 0xFFFFu, r = pk[k] >> 16;
        bufP[(H[b] & 0xFFFFu) + r] = vp[k];
    }
    #pragma unroll
    for (int k = 0; k < IPT; ++k) {
        unsigned b = ok[k] & 0xFFFFu, r = ok[k] >> 16;
        bufO[(H[b] >> 16) + r] = vo[k];
    }
    __syncthreads();

    // ---- exact within-bucket insertion cleanup (avg ~1 element/bucket) ----
    #pragma unroll 1
    for (int b = tid; b < NBINS; b += THREADS) {
        const unsigned E0 = H[b];
        const unsigned E1 = (b < NBINS - 1) ? H[b + 1]
                                            : ((unsigned)NT | ((unsigned)NT << 16));
        const int sP = (int)(E0 & 0xFFFFu), eP = (int)(E1 & 0xFFFFu);
        const int sO = (int)(E0 >> 16),     eO = (int)(E1 >> 16);

        for (int i = sP + 1; i < eP; ++i) {
            float v = bufP[i]; int j = i - 1;
            while (j >= sP && bufP[j] > v) { bufP[j + 1] = bufP[j]; --j; }
            bufP[j + 1] = v;
        }
        for (int i = sO + 1; i < eO; ++i) {
            float v = bufO[i]; int j = i - 1;
            while (j >= sO && bufO[j] > v) { bufO[j + 1] = bufO[j]; --j; }
            bufO[j + 1] = v;
        }
    }
    __syncthreads();

    // ---- coherent vectorized diff: contiguous 8 elements per thread ----
    float acc = 0.0f;
    {
        const float4* P4 = reinterpret_cast<const float4*>(bufP) + tid * 2;
        const float4* O4 = reinterpret_cast<const float4*>(bufO) + tid * 2;
        #pragma unroll
        for (int k = 0; k < 2; ++k) {
            float4 a = P4[k], c = O4[k];
            acc += fabsf(a.x - c.x) + fabsf(a.y - c.y)
                 + fabsf(a.z - c.z) + fabsf(a.w - c.w);
        }
    }
    __syncthreads();   // buffers/H reused by next pair
    return acc;
}

// Dynamic smem: bufP, bufO, H, stageP, stageO -> 5 * 16KB = 80KB
__global__ __launch_bounds__(THREADS, 2)
void wass_hybrid_kernel(const float* __restrict__ pred,
                        const float* __restrict__ obs,
                        float* __restrict__ out)
{
    extern __shared__ float smem[];
    float*    bufP   = smem;
    float*    bufO   = smem + 4096;
    unsigned* H      = reinterpret_cast<unsigned*>(smem + 8192);
    float*    stageP = smem + 12288;
    float*    stageO = smem + 16384;

    __shared__ float  sred[THREADS / 32];
    __shared__ double dred[THREADS / 32];
    __shared__ bool   s_last;

    const int tid  = threadIdx.x;
    const int tr   = blockIdx.x >> 2;
    const int c0   = (blockIdx.x & 3) * CH_PER_BLK;
    const int base = tr * CHANNELS + c0;

    // ---- load: float2 over 2 adjacent channels (L2 dedups 32B sectors).
    // ch0 -> registers, ch1 -> thread-private smem staging (no sync needed).
    float vp[IPT], vo[IPT];
    #pragma unroll
    for (int k = 0; k < IPT; ++k) {
        const int t = tid + k * THREADS;
        const size_t off = (size_t)t * COLS + base;
        float2 p = *reinterpret_cast<const float2*>(pred + off);
        float2 o = *reinterpret_cast<const float2*>(obs  + off);
        vp[k] = p.x; vo[k] = o.x;
        stageP[t] = p.y; stageO[t] = o.y;
    }

    float acc = process_pair(vp, vo, bufP, bufO, H, tid);

    #pragma unroll
    for (int k = 0; k < IPT; ++k) {
        const int t = tid + k * THREADS;
        vp[k] = stageP[t]; vo[k] = stageO[t];
    }
    acc += process_pair(vp, vo, bufP, bufO, H, tid);

    // ---- deterministic block reduction ----
    #pragma unroll
    for (int off = 16; off > 0; off >>= 1)
        acc += __shfl_xor_sync(0xFFFFFFFFu, acc, off);

    const int wid  = tid >> 5;
    const int lane = tid & 31;
    if (lane == 0) sred[wid] = acc;
    __syncthreads();

    if (wid == 0) {
        float v = (lane < THREADS / 32) ? sred[lane] : 0.0f;
        #pragma unroll
        for (int off = 8; off > 0; off >>= 1)
            v += __shfl_xor_sync(0xFFFFFFFFu, v, off);
        if (lane == 0) g_partials[blockIdx.x] = v;
    }

    // ---- last-block-done fused finalize (deterministic) ----
    if (tid == 0) {
        __threadfence();
        unsigned int t = atomicAdd(&g_done, 1u);
        s_last = (t == NBLOCKS - 1);
    }
    __syncthreads();

    if (s_last) {
        __threadfence();
        double d = 0.0;
        for (int i = tid; i < NBLOCKS; i += THREADS)
            d += (double)g_partials[i];
        #pragma unroll
        for (int off = 16; off > 0; off >>= 1)
            d += __shfl_xor_sync(0xFFFFFFFFu, d, off);
        if (lane == 0) dred[wid] = d;
        __syncthreads();
        if (wid == 0) {
            double v = (lane < THREADS / 32) ? dred[lane] : 0.0;
            #pragma unroll
            for (int off = 8; off > 0; off >>= 1)
                v += __shfl_xor_sync(0xFFFFFFFFu, v, off);
            if (lane == 0) {
                out[0] = (float)(v / ((double)NT * (double)COLS));
                g_done = 0;   // reset for next graph replay
            }
        }
    }
}

extern "C" void kernel_launch(void* const* d_in, const int* in_sizes, int n_in,
                              void* d_out, int out_size)
{
    const float* pred = (const float*)d_in[0];
    const float* obs  = (const float*)d_in[1];
    float* out = (float*)d_out;

    const size_t smem_bytes = 5 * 4096 * sizeof(float);   // 80KB
    cudaFuncSetAttribute(wass_hybrid_kernel,
                         cudaFuncAttributeMaxDynamicSharedMemorySize,
                         (int)smem_bytes);

    wass_hybrid_kernel<<<NBLOCKS, THREADS, smem_bytes>>>(pred, obs, out);
}